// round 11
// baseline (speedup 1.0000x reference)
#include <cuda_runtime.h>
#include <cuda_fp16.h>
#include <math.h>

#define NN 50000
#define EE 600000
#define DD 128
#define RR 1000
#define TT 500
#define SCAN_B 256
#define NPART  ((NN + SCAN_B - 1) / SCAN_B)   // 196

// scratch (static device globals — no allocation; zero-initialized at load)
__device__ __half g_h0[NN * DD];                // relu(features), fp16 mirror
__device__ __half g_h1[NN * DD];                // layer-1 features, fp16 mirror
__device__ __half g_hemb[(RR + TT) * DD];       // fp16 mirror of rel|time embeddings
__device__ float g_score[NN];                   // combined edge scores (only first N used)
__device__ float g_p1r[NN], g_p2r[NN], g_p1t[NN], g_p2t[NN];
__device__ float g_nrm[RR + TT];
__device__ float g_u2[2][RR + TT], g_u3[2][RR + TT];
__device__ int   g_cnt[NN];                     // zeroed by k_scatter each call
__device__ int   g_rowptr[NN + 1];
__device__ int   g_rank[EE];                    // within-row rank of each edge
__device__ int   g_ecol[EE];                    // acol values in CSR order
__device__ int   g_part[NPART];

__device__ __forceinline__ float wsum(float v) {
#pragma unroll
    for (int o = 16; o > 0; o >>= 1) v += __shfl_down_sync(0xffffffffu, v, o);
    return v;
}

__device__ __forceinline__ float dot4(float4 a, float4 b) {
    return a.x * b.x + a.y * b.y + a.z * b.z + a.w * b.w;
}

__device__ __forceinline__ uint2 pack_half4(float4 v) {
    __half2 a = __floats2half2_rn(v.x, v.y);
    __half2 b = __floats2half2_rn(v.z, v.w);
    uint2 u;
    u.x = *reinterpret_cast<unsigned*>(&a);
    u.y = *reinterpret_cast<unsigned*>(&b);
    return u;
}

__device__ __forceinline__ float4 unpack_half4(uint2 u) {
    __half2 a = *reinterpret_cast<__half2*>(&u.x);
    __half2 b = *reinterpret_cast<__half2*>(&u.y);
    float2 f1 = __half22float2(a);
    float2 f2 = __half22float2(b);
    return make_float4(f1.x, f1.y, f2.x, f2.y);
}

__device__ __forceinline__ float dot8h(uint4 a, uint4 b) {
    float4 a1 = unpack_half4(make_uint2(a.x, a.y));
    float4 a2 = unpack_half4(make_uint2(a.z, a.w));
    float4 b1 = unpack_half4(make_uint2(b.x, b.y));
    float4 b2 = unpack_half4(make_uint2(b.z, b.w));
    return dot4(a1, b1) + dot4(a2, b2);
}

// fused mega-prep:
//  warps [0, n):        out[0]=features copy, relu->g_h0 (fp16), layer-0 node dots
//  warps [n, n+r+t):    emb fp16 mirror, norm, u2/u3 for both layers
//  threads [0, e):      edge row counting; rank = atomic return value
__global__ void k_prep(const float* __restrict__ features,
                       float* __restrict__ out,
                       const float* __restrict__ rel,
                       const float* __restrict__ tim,
                       const float* __restrict__ ak,
                       const int* __restrict__ arow,
                       int n, int r, int t, int e) {
    int tid = blockIdx.x * blockDim.x + threadIdx.x;
    if (tid < e) g_rank[tid] = atomicAdd(&g_cnt[arow[tid]], 1);
    int w = tid >> 5, lane = tid & 31;
    if (w < n) {
        float4 v = reinterpret_cast<const float4*>(features)[w * 32 + lane];
        reinterpret_cast<float4*>(out)[w * 32 + lane] = v;   // output[0] = raw features
        v.x = fmaxf(v.x, 0.f); v.y = fmaxf(v.y, 0.f);
        v.z = fmaxf(v.z, 0.f); v.w = fmaxf(v.w, 0.f);
        reinterpret_cast<uint2*>(g_h0)[w * 32 + lane] = pack_half4(v);
        const float* kr = ak;
        const float* kt = ak + 3 * DD;
        float4 a1 = reinterpret_cast<const float4*>(kr)[lane];
        float4 a2 = reinterpret_cast<const float4*>(kr + DD)[lane];
        float4 b1 = reinterpret_cast<const float4*>(kt)[lane];
        float4 b2 = reinterpret_cast<const float4*>(kt + DD)[lane];
        float s1 = wsum(dot4(v, a1));
        float s2 = wsum(dot4(v, a2));
        float s3 = wsum(dot4(v, b1));
        float s4 = wsum(dot4(v, b2));
        if (lane == 0) {
            g_p1r[w] = s1; g_p2r[w] = s2;
            g_p1t[w] = s3; g_p2t[w] = s4;
        }
    } else if (w < n + r + t) {
        int q = w - n;                      // [0, r+t): rel rows first, then time rows
        int isTim = (q >= r) ? 1 : 0;
        const float* src = isTim ? (tim + (size_t)(q - r) * DD)
                                 : (rel + (size_t)q * DD);
        float4 v = reinterpret_cast<const float4*>(src)[lane];
        reinterpret_cast<uint2*>(g_hemb)[q * 32 + lane] = pack_half4(v);
        float nn = wsum(dot4(v, v));
        if (lane == 0) g_nrm[q] = sqrtf(nn);
#pragma unroll
        for (int l = 0; l < 2; l++) {
            const float* kk = ak + (size_t)(l * 2 + isTim) * 3 * DD;
            float4 k2 = reinterpret_cast<const float4*>(kk + DD)[lane];
            float4 k3 = reinterpret_cast<const float4*>(kk + 2 * DD)[lane];
            float u2 = wsum(dot4(v, k2));
            float u3 = wsum(dot4(v, k3));
            if (lane == 0) { g_u2[l][q] = u2; g_u3[l][q] = u3; }
        }
    }
}

// phase 1: per-block sums of g_cnt
__global__ void k_scan_part(int n) {
    __shared__ int sh[SCAN_B / 32];
    int i = blockIdx.x * SCAN_B + threadIdx.x;
    int v = (i < n) ? g_cnt[i] : 0;
    int s = v;
#pragma unroll
    for (int o = 16; o > 0; o >>= 1) s += __shfl_down_sync(0xffffffffu, s, o);
    int lane = threadIdx.x & 31, wid = threadIdx.x >> 5;
    if (lane == 0) sh[wid] = s;
    __syncthreads();
    if (wid == 0) {
        int t = (lane < SCAN_B / 32) ? sh[lane] : 0;
#pragma unroll
        for (int o = 16; o > 0; o >>= 1) t += __shfl_down_sync(0xffffffffu, t, o);
        if (lane == 0) g_part[blockIdx.x] = t;
    }
}

// phase 2: per-block exclusive scan; each block sums preceding partials itself
__global__ void k_scan_final(int n, int e) {
    __shared__ int sh[SCAN_B / 32];
    __shared__ int shoff;
    int tid = threadIdx.x, lane = tid & 31, wid = tid >> 5;
    int bid = blockIdx.x;

    int pv = (tid < bid) ? g_part[tid] : 0;   // NPART=196 < 256
    int ps = pv;
#pragma unroll
    for (int o = 16; o > 0; o >>= 1) ps += __shfl_down_sync(0xffffffffu, ps, o);
    if (lane == 0) sh[wid] = ps;
    __syncthreads();
    if (tid == 0) {
        int s = 0;
#pragma unroll
        for (int k = 0; k < SCAN_B / 32; k++) s += sh[k];
        shoff = s;
    }
    __syncthreads();

    int i = bid * SCAN_B + tid;
    int v = (i < n) ? g_cnt[i] : 0;
    int x = v;
#pragma unroll
    for (int o = 1; o < 32; o <<= 1) {
        int y = __shfl_up_sync(0xffffffffu, x, o);
        if (lane >= o) x += y;
    }
    if (lane == 31) sh[wid] = x;
    __syncthreads();
    if (wid == 0) {
        int s = (lane < SCAN_B / 32) ? sh[lane] : 0;
#pragma unroll
        for (int o = 1; o < 32; o <<= 1) {
            int y = __shfl_up_sync(0xffffffffu, s, o);
            if (lane >= o) s += y;
        }
        if (lane < SCAN_B / 32) sh[lane] = s;   // guarded (OOB would clobber shoff)
    }
    __syncthreads();
    int woff = (wid > 0) ? sh[wid - 1] : 0;
    int excl = x + woff - v + shoff;
    if (i < n) g_rowptr[i] = excl;
    if (i == n - 1) g_rowptr[n] = e;
}

// atomic-free scatter: position = rowptr[row] + rank; also re-zero g_cnt
__global__ void k_scatter(const int* __restrict__ arow,
                          const int* __restrict__ acol, int e, int n) {
    int i = blockIdx.x * blockDim.x + threadIdx.x;
    if (i < n) g_cnt[i] = 0;               // scans are done with counts by now
    if (i < e) {
        int p = g_rowptr[arow[i]] + g_rank[i];
        g_ecol[p] = acol[i];
    }
}

// combined edge scores; 16 lanes per edge (2 edges per warp), uint4 (8-half) loads
__global__ void k_score(const __half* __restrict__ fh,
                        const int* __restrict__ arow,
                        const int* __restrict__ acol,
                        const int* __restrict__ rcol,
                        const int* __restrict__ tcol,
                        const float* __restrict__ val,
                        int n, int r, int layer) {
    int g = (blockIdx.x * blockDim.x + threadIdx.x) >> 4;   // edge index
    int sl = threadIdx.x & 15;
    if (g >= n) return;
    int row = arow[g];
    int col = acol[g];
    int rc  = rcol[g];
    int tc  = tcol[g] + r;   // time rows live after rel rows in mirrors
    float v = val[g];
    const uint4* fh4 = reinterpret_cast<const uint4*>(fh);
    const uint4* eh4 = reinterpret_cast<const uint4*>(g_hemb);
    uint4 uf = fh4[col * 16 + sl];
    uint4 ur = eh4[rc * 16 + sl];
    uint4 ut = eh4[tc * 16 + sl];
    float dr = dot8h(uf, ur);
    float dt = dot8h(uf, ut);
#pragma unroll
    for (int o = 8; o > 0; o >>= 1) {
        dr += __shfl_down_sync(0xffffffffu, dr, o, 16);
        dt += __shfl_down_sync(0xffffffffu, dt, o, 16);
    }
    if (sl == 0) {
        float cr = v / fmaxf(v * g_nrm[rc], 1e-12f);
        float ct = v / fmaxf(v * g_nrm[tc], 1e-12f);
        float s = g_p1r[row] + g_p2r[col]
                - 2.f * cr * cr * dr * g_u2[layer][rc] + cr * g_u3[layer][rc]
                + g_p1t[row] + g_p2t[col]
                - 2.f * ct * ct * dt * g_u2[layer][tc] + ct * g_u3[layer][tc];
        g_score[g] = s;
    }
}

// one warp per row, two-pass segment softmax:
//  pass 1: lane-parallel online (m, s) over scores, warp tree-merge
//  pass 2: weighted accumulate with fixed m, unrolled x4 for MLP
__global__ void k_agg(const __half* __restrict__ fh,
                      float* __restrict__ out, int n,
                      __half* __restrict__ outh,
                      const float* __restrict__ nkr,
                      const float* __restrict__ nkt) {
    int w = (blockIdx.x * blockDim.x + threadIdx.x) >> 5;
    int lane = threadIdx.x & 31;
    if (w >= n) return;
    int beg = g_rowptr[w], end = g_rowptr[w + 1];

    // ---- pass 1: per-lane online (m, s) ----
    float m = -INFINITY, s = 0.f;
    for (int j = beg + lane; j < end; j += 32) {
        float a = g_score[g_ecol[j]];
        float nm = fmaxf(m, a);
        s = s * __expf(m - nm) + __expf(a - nm);
        m = nm;
    }
#pragma unroll
    for (int o = 16; o > 0; o >>= 1) {
        float mo = __shfl_down_sync(0xffffffffu, m, o);
        float so = __shfl_down_sync(0xffffffffu, s, o);
        float nm = fmaxf(m, mo);
        float e1 = (m  == -INFINITY) ? 0.f : __expf(m - nm);
        float e2 = (mo == -INFINITY) ? 0.f : __expf(mo - nm);
        s = s * e1 + so * e2;
        m = nm;
    }
    m = __shfl_sync(0xffffffffu, m, 0);
    s = __shfl_sync(0xffffffffu, s, 0);

    // ---- pass 2: weighted accumulate, unrolled x4 (independent gathers) ----
    float4 acc = make_float4(0.f, 0.f, 0.f, 0.f);
    int j = beg;
    for (; j + 4 <= end; j += 4) {
        int c0 = g_ecol[j];
        int c1 = g_ecol[j + 1];
        int c2 = g_ecol[j + 2];
        int c3 = g_ecol[j + 3];
        float a0 = g_score[c0];
        float a1 = g_score[c1];
        float a2 = g_score[c2];
        float a3 = g_score[c3];
        uint2 u0 = reinterpret_cast<const uint2*>(fh)[c0 * 32 + lane];
        uint2 u1 = reinterpret_cast<const uint2*>(fh)[c1 * 32 + lane];
        uint2 u2 = reinterpret_cast<const uint2*>(fh)[c2 * 32 + lane];
        uint2 u3 = reinterpret_cast<const uint2*>(fh)[c3 * 32 + lane];
        float w0 = __expf(a0 - m);
        float w1 = __expf(a1 - m);
        float w2 = __expf(a2 - m);
        float w3 = __expf(a3 - m);
        float4 f0 = unpack_half4(u0);
        float4 f1 = unpack_half4(u1);
        float4 f2 = unpack_half4(u2);
        float4 f3 = unpack_half4(u3);
        acc.x += w0 * f0.x + w1 * f1.x + w2 * f2.x + w3 * f3.x;
        acc.y += w0 * f0.y + w1 * f1.y + w2 * f2.y + w3 * f3.y;
        acc.z += w0 * f0.z + w1 * f1.z + w2 * f2.z + w3 * f3.z;
        acc.w += w0 * f0.w + w1 * f1.w + w2 * f2.w + w3 * f3.w;
    }
    for (; j < end; j++) {
        int c = g_ecol[j];
        float wt = __expf(g_score[c] - m);
        float4 fv = unpack_half4(reinterpret_cast<const uint2*>(fh)[c * 32 + lane]);
        acc.x += wt * fv.x;
        acc.y += wt * fv.y;
        acc.z += wt * fv.z;
        acc.w += wt * fv.w;
    }

    float inv = (s > 0.f) ? (1.f / s) : 0.f;
    float4 o;
    o.x = fmaxf(acc.x * inv, 0.f);
    o.y = fmaxf(acc.y * inv, 0.f);
    o.z = fmaxf(acc.z * inv, 0.f);
    o.w = fmaxf(acc.w * inv, 0.f);
    reinterpret_cast<float4*>(out)[w * 32 + lane] = o;

    if (outh) {   // fp16 mirror for next layer's gathers + fused next-layer node dots
        reinterpret_cast<uint2*>(outh)[w * 32 + lane] = pack_half4(o);
        float4 a1 = reinterpret_cast<const float4*>(nkr)[lane];
        float4 a2 = reinterpret_cast<const float4*>(nkr + DD)[lane];
        float4 b1 = reinterpret_cast<const float4*>(nkt)[lane];
        float4 b2 = reinterpret_cast<const float4*>(nkt + DD)[lane];
        float s1 = wsum(dot4(o, a1));
        float s2 = wsum(dot4(o, a2));
        float s3 = wsum(dot4(o, b1));
        float s4 = wsum(dot4(o, b2));
        if (lane == 0) {
            g_p1r[w] = s1; g_p2r[w] = s2;
            g_p1t[w] = s3; g_p2t[w] = s4;
        }
    }
}

extern "C" void kernel_launch(void* const* d_in, const int* in_sizes, int n_in,
                              void* d_out, int out_size) {
    const float* features = (const float*)d_in[0];
    const float* rel      = (const float*)d_in[1];
    const float* tim      = (const float*)d_in[2];
    const float* val      = (const float*)d_in[3];
    const float* ak       = (const float*)d_in[4];
    const int*   arow     = (const int*)d_in[5];
    const int*   acol     = (const int*)d_in[6];
    const int*   rcol     = (const int*)d_in[7];
    const int*   tcol     = (const int*)d_in[8];
    float* out = (float*)d_out;

    int n = in_sizes[0] / DD;   // 50000
    int e = in_sizes[5];        // 600000
    int r = in_sizes[1] / DD;   // 1000
    int t = in_sizes[2] / DD;   // 500

    void* h0p = nullptr; cudaGetSymbolAddress(&h0p, g_h0);
    void* h1p = nullptr; cudaGetSymbolAddress(&h1p, g_h1);
    const __half* h0 = (const __half*)h0p;
    __half* h1 = (__half*)h1p;

    int gridN  = (n * 32 + 255) / 256;   // warp per row (agg)
    int gridN16 = (n * 16 + 255) / 256;  // 16 lanes per edge (score)

    // 1: fused copy + relu + node dots + emb mirrors/dots + edge counting/ranks
    int prepWarps = n + r + t;
    k_prep<<<(prepWarps * 32 + 255) / 256, 256>>>(features, out, rel, tim, ak,
                                                  arow, n, r, t, e);
    // 2-3: two-phase scan (full-chip parallel)
    int nb = (n + SCAN_B - 1) / SCAN_B;
    k_scan_part<<<nb, SCAN_B>>>(n);
    k_scan_final<<<nb, SCAN_B>>>(n, e);
    // 4: layer-0 scores (profiled slot; CSR-independent)
    k_score<<<gridN16, 256>>>(h0, arow, acol, rcol, tcol, val, n, r, 0);
    // 5: atomic-free CSR scatter (+ restores g_cnt = 0 for next call)
    k_scatter<<<(e + 255) / 256, 256>>>(arow, acol, e, n);
    // 6: layer-0 aggregate (fuses fp16 mirror + layer-1 node dots)
    k_agg<<<gridN, 256>>>(h0, out + (size_t)n * DD, n, h1,
                          ak + (size_t)2 * 3 * DD, ak + (size_t)3 * 3 * DD);
    // 7-8: layer 1
    k_score<<<gridN16, 256>>>(h1, arow, acol, rcol, tcol, val, n, r, 1);
    k_agg<<<gridN, 256>>>(h1, out + (size_t)2 * n * DD, n, nullptr, nullptr, nullptr);
}

// round 12
// speedup vs baseline: 1.0208x; 1.0208x over previous
#include <cuda_runtime.h>
#include <cuda_fp16.h>
#include <math.h>

#define NN 50000
#define EE 600000
#define DD 128
#define RR 1000
#define TT 500
#define SCAN_B 256
#define NPART  ((NN + SCAN_B - 1) / SCAN_B)   // 196

// scratch (static device globals — no allocation; zero-initialized at load)
__device__ __half g_h0[NN * DD];                // relu(features), fp16 mirror
__device__ __half g_h1[NN * DD];                // layer-1 features, fp16 mirror
__device__ __half g_hemb[(RR + TT) * DD];       // fp16 mirror of rel|time embeddings
__device__ float g_score[NN];                   // combined edge scores (only first N used)
__device__ float g_p1r[NN], g_p2r[NN], g_p1t[NN], g_p2t[NN];
__device__ float g_nrm[RR + TT];
__device__ float g_u2[2][RR + TT], g_u3[2][RR + TT];
__device__ int   g_cnt[NN];                     // re-zeroed by the fused kernel each call
__device__ int   g_rowptr[NN + 1];
__device__ int   g_rank[EE];                    // within-row rank of each edge
__device__ int   g_ecol[EE];                    // acol values in CSR order
__device__ int   g_part[NPART];

__device__ __forceinline__ float wsum(float v) {
#pragma unroll
    for (int o = 16; o > 0; o >>= 1) v += __shfl_down_sync(0xffffffffu, v, o);
    return v;
}

__device__ __forceinline__ float dot4(float4 a, float4 b) {
    return a.x * b.x + a.y * b.y + a.z * b.z + a.w * b.w;
}

__device__ __forceinline__ uint2 pack_half4(float4 v) {
    __half2 a = __floats2half2_rn(v.x, v.y);
    __half2 b = __floats2half2_rn(v.z, v.w);
    uint2 u;
    u.x = *reinterpret_cast<unsigned*>(&a);
    u.y = *reinterpret_cast<unsigned*>(&b);
    return u;
}

__device__ __forceinline__ float4 unpack_half4(uint2 u) {
    __half2 a = *reinterpret_cast<__half2*>(&u.x);
    __half2 b = *reinterpret_cast<__half2*>(&u.y);
    float2 f1 = __half22float2(a);
    float2 f2 = __half22float2(b);
    return make_float4(f1.x, f1.y, f2.x, f2.y);
}

__device__ __forceinline__ float dot8h(uint4 a, uint4 b) {
    float4 a1 = unpack_half4(make_uint2(a.x, a.y));
    float4 a2 = unpack_half4(make_uint2(a.z, a.w));
    float4 b1 = unpack_half4(make_uint2(b.x, b.y));
    float4 b2 = unpack_half4(make_uint2(b.z, b.w));
    return dot4(a1, b1) + dot4(a2, b2);
}

// fused mega-prep:
//  warps [0, n):        out[0]=features copy, relu->g_h0 (fp16), layer-0 node dots
//  warps [n, n+r+t):    emb fp16 mirror, norm, u2/u3 for both layers
//  threads [0, e):      edge row counting; rank = atomic return value
__global__ void k_prep(const float* __restrict__ features,
                       float* __restrict__ out,
                       const float* __restrict__ rel,
                       const float* __restrict__ tim,
                       const float* __restrict__ ak,
                       const int* __restrict__ arow,
                       int n, int r, int t, int e) {
    int tid = blockIdx.x * blockDim.x + threadIdx.x;
    if (tid < e) g_rank[tid] = atomicAdd(&g_cnt[arow[tid]], 1);
    int w = tid >> 5, lane = tid & 31;
    if (w < n) {
        float4 v = reinterpret_cast<const float4*>(features)[w * 32 + lane];
        reinterpret_cast<float4*>(out)[w * 32 + lane] = v;   // output[0] = raw features
        v.x = fmaxf(v.x, 0.f); v.y = fmaxf(v.y, 0.f);
        v.z = fmaxf(v.z, 0.f); v.w = fmaxf(v.w, 0.f);
        reinterpret_cast<uint2*>(g_h0)[w * 32 + lane] = pack_half4(v);
        const float* kr = ak;
        const float* kt = ak + 3 * DD;
        float4 a1 = reinterpret_cast<const float4*>(kr)[lane];
        float4 a2 = reinterpret_cast<const float4*>(kr + DD)[lane];
        float4 b1 = reinterpret_cast<const float4*>(kt)[lane];
        float4 b2 = reinterpret_cast<const float4*>(kt + DD)[lane];
        float s1 = wsum(dot4(v, a1));
        float s2 = wsum(dot4(v, a2));
        float s3 = wsum(dot4(v, b1));
        float s4 = wsum(dot4(v, b2));
        if (lane == 0) {
            g_p1r[w] = s1; g_p2r[w] = s2;
            g_p1t[w] = s3; g_p2t[w] = s4;
        }
    } else if (w < n + r + t) {
        int q = w - n;                      // [0, r+t): rel rows first, then time rows
        int isTim = (q >= r) ? 1 : 0;
        const float* src = isTim ? (tim + (size_t)(q - r) * DD)
                                 : (rel + (size_t)q * DD);
        float4 v = reinterpret_cast<const float4*>(src)[lane];
        reinterpret_cast<uint2*>(g_hemb)[q * 32 + lane] = pack_half4(v);
        float nn = wsum(dot4(v, v));
        if (lane == 0) g_nrm[q] = sqrtf(nn);
#pragma unroll
        for (int l = 0; l < 2; l++) {
            const float* kk = ak + (size_t)(l * 2 + isTim) * 3 * DD;
            float4 k2 = reinterpret_cast<const float4*>(kk + DD)[lane];
            float4 k3 = reinterpret_cast<const float4*>(kk + 2 * DD)[lane];
            float u2 = wsum(dot4(v, k2));
            float u3 = wsum(dot4(v, k3));
            if (lane == 0) { g_u2[l][q] = u2; g_u3[l][q] = u3; }
        }
    }
}

// phase 1: per-block sums of g_cnt
__global__ void k_scan_part(int n) {
    __shared__ int sh[SCAN_B / 32];
    int i = blockIdx.x * SCAN_B + threadIdx.x;
    int v = (i < n) ? g_cnt[i] : 0;
    int s = v;
#pragma unroll
    for (int o = 16; o > 0; o >>= 1) s += __shfl_down_sync(0xffffffffu, s, o);
    int lane = threadIdx.x & 31, wid = threadIdx.x >> 5;
    if (lane == 0) sh[wid] = s;
    __syncthreads();
    if (wid == 0) {
        int t = (lane < SCAN_B / 32) ? sh[lane] : 0;
#pragma unroll
        for (int o = 16; o > 0; o >>= 1) t += __shfl_down_sync(0xffffffffu, t, o);
        if (lane == 0) g_part[blockIdx.x] = t;
    }
}

// phase 2: per-block exclusive scan; each block sums preceding partials itself
__global__ void k_scan_final(int n, int e) {
    __shared__ int sh[SCAN_B / 32];
    __shared__ int shoff;
    int tid = threadIdx.x, lane = tid & 31, wid = tid >> 5;
    int bid = blockIdx.x;

    int pv = (tid < bid) ? g_part[tid] : 0;   // NPART=196 < 256
    int ps = pv;
#pragma unroll
    for (int o = 16; o > 0; o >>= 1) ps += __shfl_down_sync(0xffffffffu, ps, o);
    if (lane == 0) sh[wid] = ps;
    __syncthreads();
    if (tid == 0) {
        int s = 0;
#pragma unroll
        for (int k = 0; k < SCAN_B / 32; k++) s += sh[k];
        shoff = s;
    }
    __syncthreads();

    int i = bid * SCAN_B + tid;
    int v = (i < n) ? g_cnt[i] : 0;
    int x = v;
#pragma unroll
    for (int o = 1; o < 32; o <<= 1) {
        int y = __shfl_up_sync(0xffffffffu, x, o);
        if (lane >= o) x += y;
    }
    if (lane == 31) sh[wid] = x;
    __syncthreads();
    if (wid == 0) {
        int s = (lane < SCAN_B / 32) ? sh[lane] : 0;
#pragma unroll
        for (int o = 1; o < 32; o <<= 1) {
            int y = __shfl_up_sync(0xffffffffu, s, o);
            if (lane >= o) s += y;
        }
        if (lane < SCAN_B / 32) sh[lane] = s;   // guarded (OOB would clobber shoff)
    }
    __syncthreads();
    int woff = (wid > 0) ? sh[wid - 1] : 0;
    int excl = x + woff - v + shoff;
    if (i < n) g_rowptr[i] = excl;
    if (i == n - 1) g_rowptr[n] = e;
}

// fused: 16-lane edge scores (groups [0,n)) + atomic-free CSR scatter (threads [0,e))
// The two roles are independent; scatter traffic hides in score's gather stalls.
__global__ void k_score_scatter(const __half* __restrict__ fh,
                                const int* __restrict__ arow,
                                const int* __restrict__ acol,
                                const int* __restrict__ rcol,
                                const int* __restrict__ tcol,
                                const float* __restrict__ val,
                                int n, int r, int layer, int e) {
    int tid = blockIdx.x * blockDim.x + threadIdx.x;
    if (e > 0) {                            // layer-0 call also performs scatter
        if (tid < n) g_cnt[tid] = 0;        // restore counts for next kernel_launch
        if (tid < e) {
            int p = g_rowptr[arow[tid]] + g_rank[tid];
            g_ecol[p] = acol[tid];
        }
    }
    int g = tid >> 4;                       // edge index for scoring
    int sl = tid & 15;
    if (g >= n) return;
    int row = arow[g];
    int col = acol[g];
    int rc  = rcol[g];
    int tc  = tcol[g] + r;   // time rows live after rel rows in mirrors
    float v = val[g];
    const uint4* fh4 = reinterpret_cast<const uint4*>(fh);
    const uint4* eh4 = reinterpret_cast<const uint4*>(g_hemb);
    uint4 uf = fh4[col * 16 + sl];
    uint4 ur = eh4[rc * 16 + sl];
    uint4 ut = eh4[tc * 16 + sl];
    float dr = dot8h(uf, ur);
    float dt = dot8h(uf, ut);
#pragma unroll
    for (int o = 8; o > 0; o >>= 1) {
        dr += __shfl_down_sync(0xffffffffu, dr, o, 16);
        dt += __shfl_down_sync(0xffffffffu, dt, o, 16);
    }
    if (sl == 0) {
        float cr = v / fmaxf(v * g_nrm[rc], 1e-12f);
        float ct = v / fmaxf(v * g_nrm[tc], 1e-12f);
        float s = g_p1r[row] + g_p2r[col]
                - 2.f * cr * cr * dr * g_u2[layer][rc] + cr * g_u3[layer][rc]
                + g_p1t[row] + g_p2t[col]
                - 2.f * ct * ct * dt * g_u2[layer][tc] + ct * g_u3[layer][tc];
        g_score[g] = s;
    }
}

// one warp per row, two-pass segment softmax:
//  pass 1: lane-parallel online (m, s) over scores, warp tree-merge
//  pass 2: weighted accumulate with fixed m, unrolled x4 for MLP
__global__ void k_agg(const __half* __restrict__ fh,
                      float* __restrict__ out, int n,
                      __half* __restrict__ outh,
                      const float* __restrict__ nkr,
                      const float* __restrict__ nkt) {
    int w = (blockIdx.x * blockDim.x + threadIdx.x) >> 5;
    int lane = threadIdx.x & 31;
    if (w >= n) return;
    int beg = g_rowptr[w], end = g_rowptr[w + 1];

    // ---- pass 1: per-lane online (m, s) ----
    float m = -INFINITY, s = 0.f;
    for (int j = beg + lane; j < end; j += 32) {
        float a = g_score[g_ecol[j]];
        float nm = fmaxf(m, a);
        s = s * __expf(m - nm) + __expf(a - nm);
        m = nm;
    }
#pragma unroll
    for (int o = 16; o > 0; o >>= 1) {
        float mo = __shfl_down_sync(0xffffffffu, m, o);
        float so = __shfl_down_sync(0xffffffffu, s, o);
        float nm = fmaxf(m, mo);
        float e1 = (m  == -INFINITY) ? 0.f : __expf(m - nm);
        float e2 = (mo == -INFINITY) ? 0.f : __expf(mo - nm);
        s = s * e1 + so * e2;
        m = nm;
    }
    m = __shfl_sync(0xffffffffu, m, 0);
    s = __shfl_sync(0xffffffffu, s, 0);

    // ---- pass 2: weighted accumulate, unrolled x4 (independent gathers) ----
    float4 acc = make_float4(0.f, 0.f, 0.f, 0.f);
    int j = beg;
    for (; j + 4 <= end; j += 4) {
        int c0 = g_ecol[j];
        int c1 = g_ecol[j + 1];
        int c2 = g_ecol[j + 2];
        int c3 = g_ecol[j + 3];
        float a0 = g_score[c0];
        float a1 = g_score[c1];
        float a2 = g_score[c2];
        float a3 = g_score[c3];
        uint2 u0 = reinterpret_cast<const uint2*>(fh)[c0 * 32 + lane];
        uint2 u1 = reinterpret_cast<const uint2*>(fh)[c1 * 32 + lane];
        uint2 u2 = reinterpret_cast<const uint2*>(fh)[c2 * 32 + lane];
        uint2 u3 = reinterpret_cast<const uint2*>(fh)[c3 * 32 + lane];
        float w0 = __expf(a0 - m);
        float w1 = __expf(a1 - m);
        float w2 = __expf(a2 - m);
        float w3 = __expf(a3 - m);
        float4 f0 = unpack_half4(u0);
        float4 f1 = unpack_half4(u1);
        float4 f2 = unpack_half4(u2);
        float4 f3 = unpack_half4(u3);
        acc.x += w0 * f0.x + w1 * f1.x + w2 * f2.x + w3 * f3.x;
        acc.y += w0 * f0.y + w1 * f1.y + w2 * f2.y + w3 * f3.y;
        acc.z += w0 * f0.z + w1 * f1.z + w2 * f2.z + w3 * f3.z;
        acc.w += w0 * f0.w + w1 * f1.w + w2 * f2.w + w3 * f3.w;
    }
    for (; j < end; j++) {
        int c = g_ecol[j];
        float wt = __expf(g_score[c] - m);
        float4 fv = unpack_half4(reinterpret_cast<const uint2*>(fh)[c * 32 + lane]);
        acc.x += wt * fv.x;
        acc.y += wt * fv.y;
        acc.z += wt * fv.z;
        acc.w += wt * fv.w;
    }

    float inv = (s > 0.f) ? (1.f / s) : 0.f;
    float4 o;
    o.x = fmaxf(acc.x * inv, 0.f);
    o.y = fmaxf(acc.y * inv, 0.f);
    o.z = fmaxf(acc.z * inv, 0.f);
    o.w = fmaxf(acc.w * inv, 0.f);
    reinterpret_cast<float4*>(out)[w * 32 + lane] = o;

    if (outh) {   // fp16 mirror for next layer's gathers + fused next-layer node dots
        reinterpret_cast<uint2*>(outh)[w * 32 + lane] = pack_half4(o);
        float4 a1 = reinterpret_cast<const float4*>(nkr)[lane];
        float4 a2 = reinterpret_cast<const float4*>(nkr + DD)[lane];
        float4 b1 = reinterpret_cast<const float4*>(nkt)[lane];
        float4 b2 = reinterpret_cast<const float4*>(nkt + DD)[lane];
        float s1 = wsum(dot4(o, a1));
        float s2 = wsum(dot4(o, a2));
        float s3 = wsum(dot4(o, b1));
        float s4 = wsum(dot4(o, b2));
        if (lane == 0) {
            g_p1r[w] = s1; g_p2r[w] = s2;
            g_p1t[w] = s3; g_p2t[w] = s4;
        }
    }
}

extern "C" void kernel_launch(void* const* d_in, const int* in_sizes, int n_in,
                              void* d_out, int out_size) {
    const float* features = (const float*)d_in[0];
    const float* rel      = (const float*)d_in[1];
    const float* tim      = (const float*)d_in[2];
    const float* val      = (const float*)d_in[3];
    const float* ak       = (const float*)d_in[4];
    const int*   arow     = (const int*)d_in[5];
    const int*   acol     = (const int*)d_in[6];
    const int*   rcol     = (const int*)d_in[7];
    const int*   tcol     = (const int*)d_in[8];
    float* out = (float*)d_out;

    int n = in_sizes[0] / DD;   // 50000
    int e = in_sizes[5];        // 600000
    int r = in_sizes[1] / DD;   // 1000
    int t = in_sizes[2] / DD;   // 500

    void* h0p = nullptr; cudaGetSymbolAddress(&h0p, g_h0);
    void* h1p = nullptr; cudaGetSymbolAddress(&h1p, g_h1);
    const __half* h0 = (const __half*)h0p;
    __half* h1 = (__half*)h1p;

    int gridN  = (n * 32 + 255) / 256;                 // warp per row (agg)
    int fusedThreads = max(n * 16, e);                 // score groups + scatter threads
    int gridF = (fusedThreads + 255) / 256;
    int gridN16 = (n * 16 + 255) / 256;                // score-only (layer 1)

    // 1: fused copy + relu + node dots + emb mirrors/dots + edge counting/ranks
    int prepWarps = n + r + t;
    k_prep<<<(prepWarps * 32 + 255) / 256, 256>>>(features, out, rel, tim, ak,
                                                  arow, n, r, t, e);
    // 2-3: two-phase scan (full-chip parallel)
    int nb = (n + SCAN_B - 1) / SCAN_B;
    k_scan_part<<<nb, SCAN_B>>>(n);
    k_scan_final<<<nb, SCAN_B>>>(n, e);
    // 4: fused layer-0 scores + CSR scatter (+ g_cnt restore) [profiled slot]
    k_score_scatter<<<gridF, 256>>>(h0, arow, acol, rcol, tcol, val, n, r, 0, e);
    // 5: layer-0 aggregate (fuses fp16 mirror + layer-1 node dots)
    k_agg<<<gridN, 256>>>(h0, out + (size_t)n * DD, n, h1,
                          ak + (size_t)2 * 3 * DD, ak + (size_t)3 * 3 * DD);
    // 6-7: layer 1
    k_score_scatter<<<gridN16, 256>>>(h1, arow, acol, rcol, tcol, val, n, r, 1, 0);
    k_agg<<<gridN, 256>>>(h1, out + (size_t)2 * n * DD, n, nullptr, nullptr, nullptr);
}

// round 13
// speedup vs baseline: 1.0780x; 1.0561x over previous
#include <cuda_runtime.h>
#include <cuda_fp16.h>
#include <math.h>

#define NN 50000
#define EE 600000
#define DD 128
#define RR 1000
#define TT 500
#define SCAN_B 256
#define NPART  ((NN + SCAN_B - 1) / SCAN_B)   // 196

// scratch (static device globals — no allocation; zero-initialized at load)
__device__ __half g_h0[NN * DD];                // relu(features), fp16 mirror
__device__ __half g_h1[NN * DD];                // layer-1 features, fp16 mirror
__device__ __half g_hemb[(RR + TT) * DD];       // fp16 mirror of rel|time embeddings
__device__ float g_score[NN];                   // combined edge scores (only first N used)
__device__ float g_p1r[NN], g_p2r[NN], g_p1t[NN], g_p2t[NN];
__device__ float g_nrm[RR + TT];
__device__ float g_u2[2][RR + TT], g_u3[2][RR + TT];
__device__ int   g_cnt[NN];                     // re-zeroed by score_scatter each call
__device__ int   g_rowptr[NN + 1];
__device__ int   g_rank[EE];                    // within-row rank of each edge
__device__ int   g_ecol[EE];                    // acol values in CSR order
__device__ int   g_part[NPART];                 // lookback flags: 0=pending, sum+1=ready

__device__ __forceinline__ float wsum(float v) {
#pragma unroll
    for (int o = 16; o > 0; o >>= 1) v += __shfl_down_sync(0xffffffffu, v, o);
    return v;
}

__device__ __forceinline__ float dot4(float4 a, float4 b) {
    return a.x * b.x + a.y * b.y + a.z * b.z + a.w * b.w;
}

__device__ __forceinline__ uint2 pack_half4(float4 v) {
    __half2 a = __floats2half2_rn(v.x, v.y);
    __half2 b = __floats2half2_rn(v.z, v.w);
    uint2 u;
    u.x = *reinterpret_cast<unsigned*>(&a);
    u.y = *reinterpret_cast<unsigned*>(&b);
    return u;
}

__device__ __forceinline__ float4 unpack_half4(uint2 u) {
    __half2 a = *reinterpret_cast<__half2*>(&u.x);
    __half2 b = *reinterpret_cast<__half2*>(&u.y);
    float2 f1 = __half22float2(a);
    float2 f2 = __half22float2(b);
    return make_float4(f1.x, f1.y, f2.x, f2.y);
}

__device__ __forceinline__ float dot8h(uint4 a, uint4 b) {
    float4 a1 = unpack_half4(make_uint2(a.x, a.y));
    float4 a2 = unpack_half4(make_uint2(a.z, a.w));
    float4 b1 = unpack_half4(make_uint2(b.x, b.y));
    float4 b2 = unpack_half4(make_uint2(b.z, b.w));
    return dot4(a1, b1) + dot4(a2, b2);
}

// fused mega-prep:
//  warps [0, n):        out[0]=features copy, relu->g_h0 (fp16), layer-0 node dots
//  warps [n, n+r+t):    emb fp16 mirror, norm, u2/u3 for both layers
//  threads [0, e):      edge row counting; rank = atomic return value
__global__ void k_prep(const float* __restrict__ features,
                       float* __restrict__ out,
                       const float* __restrict__ rel,
                       const float* __restrict__ tim,
                       const float* __restrict__ ak,
                       const int* __restrict__ arow,
                       int n, int r, int t, int e) {
    int tid = blockIdx.x * blockDim.x + threadIdx.x;
    if (tid < e) g_rank[tid] = atomicAdd(&g_cnt[arow[tid]], 1);
    int w = tid >> 5, lane = tid & 31;
    if (w < n) {
        float4 v = reinterpret_cast<const float4*>(features)[w * 32 + lane];
        reinterpret_cast<float4*>(out)[w * 32 + lane] = v;   // output[0] = raw features
        v.x = fmaxf(v.x, 0.f); v.y = fmaxf(v.y, 0.f);
        v.z = fmaxf(v.z, 0.f); v.w = fmaxf(v.w, 0.f);
        reinterpret_cast<uint2*>(g_h0)[w * 32 + lane] = pack_half4(v);
        const float* kr = ak;
        const float* kt = ak + 3 * DD;
        float4 a1 = reinterpret_cast<const float4*>(kr)[lane];
        float4 a2 = reinterpret_cast<const float4*>(kr + DD)[lane];
        float4 b1 = reinterpret_cast<const float4*>(kt)[lane];
        float4 b2 = reinterpret_cast<const float4*>(kt + DD)[lane];
        float s1 = wsum(dot4(v, a1));
        float s2 = wsum(dot4(v, a2));
        float s3 = wsum(dot4(v, b1));
        float s4 = wsum(dot4(v, b2));
        if (lane == 0) {
            g_p1r[w] = s1; g_p2r[w] = s2;
            g_p1t[w] = s3; g_p2t[w] = s4;
        }
    } else if (w < n + r + t) {
        int q = w - n;                      // [0, r+t): rel rows first, then time rows
        int isTim = (q >= r) ? 1 : 0;
        const float* src = isTim ? (tim + (size_t)(q - r) * DD)
                                 : (rel + (size_t)q * DD);
        float4 v = reinterpret_cast<const float4*>(src)[lane];
        reinterpret_cast<uint2*>(g_hemb)[q * 32 + lane] = pack_half4(v);
        float nn = wsum(dot4(v, v));
        if (lane == 0) g_nrm[q] = sqrtf(nn);
#pragma unroll
        for (int l = 0; l < 2; l++) {
            const float* kk = ak + (size_t)(l * 2 + isTim) * 3 * DD;
            float4 k2 = reinterpret_cast<const float4*>(kk + DD)[lane];
            float4 k3 = reinterpret_cast<const float4*>(kk + 2 * DD)[lane];
            float u2 = wsum(dot4(v, k2));
            float u3 = wsum(dot4(v, k3));
            if (lane == 0) { g_u2[l][q] = u2; g_u3[l][q] = u3; }
        }
    }
}

// single-launch scan with decoupled lookback:
//  each block publishes its partial sum (flag = sum+1), spins on predecessors.
//  All NPART=196 blocks are co-resident in wave 1 -> no deadlock.
__global__ void k_scan(int n, int e) {
    __shared__ int sh[SCAN_B / 32];
    __shared__ int shoff;
    int tid = threadIdx.x, lane = tid & 31, wid = tid >> 5;
    int bid = blockIdx.x;
    int i = bid * SCAN_B + tid;
    int v = (i < n) ? g_cnt[i] : 0;

    // 1. publish this block's sum (flag before any waiting -> deadlock-free)
    int bs = v;
#pragma unroll
    for (int o = 16; o > 0; o >>= 1) bs += __shfl_down_sync(0xffffffffu, bs, o);
    if (lane == 0) sh[wid] = bs;
    __syncthreads();
    if (tid == 0) {
        int s = 0;
#pragma unroll
        for (int k = 0; k < SCAN_B / 32; k++) s += sh[k];
        atomicExch(&g_part[bid], s + 1);
    }
    __syncthreads();

    // 2. lookback: thread tid spins on predecessor tid (tid < bid <= 195 < 256)
    int pv = 0;
    if (tid < bid) {
        int x;
        do { x = atomicAdd(&g_part[tid], 0); } while (x == 0);
        pv = x - 1;
    }
    int ps = pv;
#pragma unroll
    for (int o = 16; o > 0; o >>= 1) ps += __shfl_down_sync(0xffffffffu, ps, o);
    if (lane == 0) sh[wid] = ps;
    __syncthreads();
    if (tid == 0) {
        int s = 0;
#pragma unroll
        for (int k = 0; k < SCAN_B / 32; k++) s += sh[k];
        shoff = s;
    }
    __syncthreads();

    // 3. per-block exclusive scan
    int x = v;
#pragma unroll
    for (int o = 1; o < 32; o <<= 1) {
        int y = __shfl_up_sync(0xffffffffu, x, o);
        if (lane >= o) x += y;
    }
    if (lane == 31) sh[wid] = x;
    __syncthreads();
    if (wid == 0) {
        int s = (lane < SCAN_B / 32) ? sh[lane] : 0;
#pragma unroll
        for (int o = 1; o < 32; o <<= 1) {
            int y = __shfl_up_sync(0xffffffffu, s, o);
            if (lane >= o) s += y;
        }
        if (lane < SCAN_B / 32) sh[lane] = s;
    }
    __syncthreads();
    int woff = (wid > 0) ? sh[wid - 1] : 0;
    int excl = x + woff - v + shoff;
    if (i < n) g_rowptr[i] = excl;
    if (i == n - 1) g_rowptr[n] = e;
}

// fused: 16-lane edge scores (groups [0,n)) + atomic-free CSR scatter (threads [0,e))
// Also restores g_cnt and g_part to zero for the next kernel_launch call.
__global__ void k_score_scatter(const __half* __restrict__ fh,
                                const int* __restrict__ arow,
                                const int* __restrict__ acol,
                                const int* __restrict__ rcol,
                                const int* __restrict__ tcol,
                                const float* __restrict__ val,
                                int n, int r, int layer, int e) {
    int tid = blockIdx.x * blockDim.x + threadIdx.x;
    if (e > 0) {                            // layer-0 call also performs scatter
        if (tid < n) g_cnt[tid] = 0;        // restore for next call
        if (tid < NPART) g_part[tid] = 0;   // restore lookback flags
        if (tid < e) {
            int p = g_rowptr[arow[tid]] + g_rank[tid];
            g_ecol[p] = acol[tid];
        }
    }
    int g = tid >> 4;                       // edge index for scoring
    int sl = tid & 15;
    if (g >= n) return;
    int row = arow[g];
    int col = acol[g];
    int rc  = rcol[g];
    int tc  = tcol[g] + r;   // time rows live after rel rows in mirrors
    float v = val[g];
    const uint4* fh4 = reinterpret_cast<const uint4*>(fh);
    const uint4* eh4 = reinterpret_cast<const uint4*>(g_hemb);
    uint4 uf = fh4[col * 16 + sl];
    uint4 ur = eh4[rc * 16 + sl];
    uint4 ut = eh4[tc * 16 + sl];
    float dr = dot8h(uf, ur);
    float dt = dot8h(uf, ut);
#pragma unroll
    for (int o = 8; o > 0; o >>= 1) {
        dr += __shfl_down_sync(0xffffffffu, dr, o, 16);
        dt += __shfl_down_sync(0xffffffffu, dt, o, 16);
    }
    if (sl == 0) {
        float cr = v / fmaxf(v * g_nrm[rc], 1e-12f);
        float ct = v / fmaxf(v * g_nrm[tc], 1e-12f);
        float s = g_p1r[row] + g_p2r[col]
                - 2.f * cr * cr * dr * g_u2[layer][rc] + cr * g_u3[layer][rc]
                + g_p1t[row] + g_p2t[col]
                - 2.f * ct * ct * dt * g_u2[layer][tc] + ct * g_u3[layer][tc];
        g_score[g] = s;
    }
}

// one warp per row, two-pass segment softmax:
//  pass 1: lane-parallel online (m, s) over scores, warp tree-merge
//  pass 2: owning lane computes 1 exp/edge, stages (col, weight) in smem,
//          all lanes consume broadcast reads (kills 32x-redundant MUFU)
__global__ void k_agg(const __half* __restrict__ fh,
                      float* __restrict__ out, int n,
                      __half* __restrict__ outh,
                      const float* __restrict__ nkr,
                      const float* __restrict__ nkt) {
    __shared__ float swt[8][32];
    __shared__ int   scl[8][32];
    int w = (blockIdx.x * blockDim.x + threadIdx.x) >> 5;
    int lane = threadIdx.x & 31;
    int wid = threadIdx.x >> 5;
    if (w >= n) return;
    int beg = g_rowptr[w], end = g_rowptr[w + 1];
    int deg = end - beg;

    // ---- pass 1: per-lane online (m, s) ----
    float m = -INFINITY, s = 0.f;
    for (int j = beg + lane; j < end; j += 32) {
        float a = g_score[g_ecol[j]];
        float nm = fmaxf(m, a);
        s = s * __expf(m - nm) + __expf(a - nm);
        m = nm;
    }
#pragma unroll
    for (int o = 16; o > 0; o >>= 1) {
        float mo = __shfl_down_sync(0xffffffffu, m, o);
        float so = __shfl_down_sync(0xffffffffu, s, o);
        float nm = fmaxf(m, mo);
        float e1 = (m  == -INFINITY) ? 0.f : __expf(m - nm);
        float e2 = (mo == -INFINITY) ? 0.f : __expf(mo - nm);
        s = s * e1 + so * e2;
        m = nm;
    }
    m = __shfl_sync(0xffffffffu, m, 0);
    s = __shfl_sync(0xffffffffu, s, 0);

    // ---- pass 2: staged weights, broadcast consume ----
    float4 acc = make_float4(0.f, 0.f, 0.f, 0.f);
    for (int base = 0; base < deg; base += 32) {
        int j = beg + base + lane;
        if (j < end) {
            int c = g_ecol[j];
            scl[wid][lane] = c;
            swt[wid][lane] = __expf(g_score[c] - m);
        }
        __syncwarp();
        int lim = min(32, deg - base);
#pragma unroll 4
        for (int k = 0; k < lim; k++) {
            float wk = swt[wid][k];
            int   ck = scl[wid][k];
            float4 fv = unpack_half4(reinterpret_cast<const uint2*>(fh)[ck * 32 + lane]);
            acc.x += wk * fv.x;
            acc.y += wk * fv.y;
            acc.z += wk * fv.z;
            acc.w += wk * fv.w;
        }
        __syncwarp();
    }

    float inv = (s > 0.f) ? (1.f / s) : 0.f;
    float4 o;
    o.x = fmaxf(acc.x * inv, 0.f);
    o.y = fmaxf(acc.y * inv, 0.f);
    o.z = fmaxf(acc.z * inv, 0.f);
    o.w = fmaxf(acc.w * inv, 0.f);
    reinterpret_cast<float4*>(out)[w * 32 + lane] = o;

    if (outh) {   // fp16 mirror for next layer's gathers + fused next-layer node dots
        reinterpret_cast<uint2*>(outh)[w * 32 + lane] = pack_half4(o);
        float4 a1 = reinterpret_cast<const float4*>(nkr)[lane];
        float4 a2 = reinterpret_cast<const float4*>(nkr + DD)[lane];
        float4 b1 = reinterpret_cast<const float4*>(nkt)[lane];
        float4 b2 = reinterpret_cast<const float4*>(nkt + DD)[lane];
        float s1 = wsum(dot4(o, a1));
        float s2 = wsum(dot4(o, a2));
        float s3 = wsum(dot4(o, b1));
        float s4 = wsum(dot4(o, b2));
        if (lane == 0) {
            g_p1r[w] = s1; g_p2r[w] = s2;
            g_p1t[w] = s3; g_p2t[w] = s4;
        }
    }
}

extern "C" void kernel_launch(void* const* d_in, const int* in_sizes, int n_in,
                              void* d_out, int out_size) {
    const float* features = (const float*)d_in[0];
    const float* rel      = (const float*)d_in[1];
    const float* tim      = (const float*)d_in[2];
    const float* val      = (const float*)d_in[3];
    const float* ak       = (const float*)d_in[4];
    const int*   arow     = (const int*)d_in[5];
    const int*   acol     = (const int*)d_in[6];
    const int*   rcol     = (const int*)d_in[7];
    const int*   tcol     = (const int*)d_in[8];
    float* out = (float*)d_out;

    int n = in_sizes[0] / DD;   // 50000
    int e = in_sizes[5];        // 600000
    int r = in_sizes[1] / DD;   // 1000
    int t = in_sizes[2] / DD;   // 500

    void* h0p = nullptr; cudaGetSymbolAddress(&h0p, g_h0);
    void* h1p = nullptr; cudaGetSymbolAddress(&h1p, g_h1);
    const __half* h0 = (const __half*)h0p;
    __half* h1 = (__half*)h1p;

    int gridN  = (n * 32 + 255) / 256;                 // warp per row (agg)
    int fusedThreads = max(n * 16, e);                 // score groups + scatter threads
    int gridF = (fusedThreads + 255) / 256;
    int gridN16 = (n * 16 + 255) / 256;                // score-only (layer 1)

    // 1: fused copy + relu + node dots + emb mirrors/dots + edge counting/ranks
    int prepWarps = n + r + t;
    k_prep<<<(prepWarps * 32 + 255) / 256, 256>>>(features, out, rel, tim, ak,
                                                  arow, n, r, t, e);
    // 2: single-launch lookback scan
    k_scan<<<NPART, SCAN_B>>>(n, e);
    // 3: fused layer-0 scores + CSR scatter (+ g_cnt/g_part restore)
    k_score_scatter<<<gridF, 256>>>(h0, arow, acol, rcol, tcol, val, n, r, 0, e);
    // 4: layer-0 aggregate (PROFILED SLOT; fuses fp16 mirror + layer-1 node dots)
    k_agg<<<gridN, 256>>>(h0, out + (size_t)n * DD, n, h1,
                          ak + (size_t)2 * 3 * DD, ak + (size_t)3 * 3 * DD);
    // 5-6: layer 1
    k_score_scatter<<<gridN16, 256>>>(h1, arow, acol, rcol, tcol, val, n, r, 1, 0);
    k_agg<<<gridN, 256>>>(h1, out + (size_t)2 * n * DD, n, nullptr, nullptr, nullptr);
}

// round 14
// speedup vs baseline: 1.1425x; 1.0598x over previous
#include <cuda_runtime.h>
#include <cuda_fp16.h>
#include <math.h>

#define NN 50000
#define EE 600000
#define DD 128
#define RR 1000
#define TT 500
#define SCAN_B 256
#define NPART  ((NN + SCAN_B - 1) / SCAN_B)   // 196

// scratch (static device globals — no allocation; zero-initialized at load)
__device__ __half g_h0[NN * DD];                // relu(features), fp16 mirror
__device__ __half g_h1[NN * DD];                // layer-1 features, fp16 mirror
__device__ __half g_hemb[(RR + TT) * DD];       // fp16 mirror of rel|time embeddings
__device__ float g_score[NN];                   // combined edge scores (only first N used)
__device__ float g_p1r[NN], g_p2r[NN], g_p1t[NN], g_p2t[NN];
__device__ float g_nrm[RR + TT];
__device__ float g_u2[2][RR + TT], g_u3[2][RR + TT];
__device__ int   g_cnt[NN];                     // re-zeroed by score_scatter each call
__device__ int   g_rowptr[NN + 1];
__device__ int   g_rank[EE];                    // within-row rank of each edge
__device__ int   g_ecol[EE];                    // acol values in CSR order
__device__ int   g_part[NPART];                 // lookback flags: 0=pending, sum+1=ready

__device__ __forceinline__ float wsum(float v) {
#pragma unroll
    for (int o = 16; o > 0; o >>= 1) v += __shfl_down_sync(0xffffffffu, v, o);
    return v;
}

__device__ __forceinline__ float dot4(float4 a, float4 b) {
    return a.x * b.x + a.y * b.y + a.z * b.z + a.w * b.w;
}

__device__ __forceinline__ uint2 pack_half4(float4 v) {
    __half2 a = __floats2half2_rn(v.x, v.y);
    __half2 b = __floats2half2_rn(v.z, v.w);
    uint2 u;
    u.x = *reinterpret_cast<unsigned*>(&a);
    u.y = *reinterpret_cast<unsigned*>(&b);
    return u;
}

__device__ __forceinline__ float4 unpack_half4(uint2 u) {
    __half2 a = *reinterpret_cast<__half2*>(&u.x);
    __half2 b = *reinterpret_cast<__half2*>(&u.y);
    float2 f1 = __half22float2(a);
    float2 f2 = __half22float2(b);
    return make_float4(f1.x, f1.y, f2.x, f2.y);
}

__device__ __forceinline__ float dot8h(uint4 a, uint4 b) {
    float4 a1 = unpack_half4(make_uint2(a.x, a.y));
    float4 a2 = unpack_half4(make_uint2(a.z, a.w));
    float4 b1 = unpack_half4(make_uint2(b.x, b.y));
    float4 b2 = unpack_half4(make_uint2(b.z, b.w));
    return dot4(a1, b1) + dot4(a2, b2);
}

// packed f32x2 FMA: acc = a * b + acc   (2 fp32 lanes in one instruction)
#define FMA_F32X2(acc, a, b) \
    asm("fma.rn.f32x2 %0, %1, %2, %0;" : "+l"(acc) : "l"(a), "l"(b))

__device__ __forceinline__ unsigned long long pack_f32x2(float lo, float hi) {
    unsigned long long u;
    asm("mov.b64 %0, {%1, %2};" : "=l"(u) : "f"(lo), "f"(hi));
    return u;
}

__device__ __forceinline__ float2 unpack_f32x2(unsigned long long u) {
    float lo, hi;
    asm("mov.b64 {%0, %1}, %2;" : "=f"(lo), "=f"(hi) : "l"(u));
    return make_float2(lo, hi);
}

// half2 pair -> packed f32x2 pair
__device__ __forceinline__ void h4_to_f32x2(uint2 u, unsigned long long& p1,
                                            unsigned long long& p2) {
    float2 f1 = __half22float2(*reinterpret_cast<__half2*>(&u.x));
    float2 f2 = __half22float2(*reinterpret_cast<__half2*>(&u.y));
    p1 = pack_f32x2(f1.x, f1.y);
    p2 = pack_f32x2(f2.x, f2.y);
}

// fused mega-prep:
//  warps [0, n):        out[0]=features copy, relu->g_h0 (fp16), layer-0 node dots
//  warps [n, n+r+t):    emb fp16 mirror, norm, u2/u3 for both layers
//  threads [0, e):      edge row counting; rank = atomic return value
__global__ void k_prep(const float* __restrict__ features,
                       float* __restrict__ out,
                       const float* __restrict__ rel,
                       const float* __restrict__ tim,
                       const float* __restrict__ ak,
                       const int* __restrict__ arow,
                       int n, int r, int t, int e) {
    int tid = blockIdx.x * blockDim.x + threadIdx.x;
    if (tid < e) g_rank[tid] = atomicAdd(&g_cnt[arow[tid]], 1);
    int w = tid >> 5, lane = tid & 31;
    if (w < n) {
        float4 v = reinterpret_cast<const float4*>(features)[w * 32 + lane];
        reinterpret_cast<float4*>(out)[w * 32 + lane] = v;   // output[0] = raw features
        v.x = fmaxf(v.x, 0.f); v.y = fmaxf(v.y, 0.f);
        v.z = fmaxf(v.z, 0.f); v.w = fmaxf(v.w, 0.f);
        reinterpret_cast<uint2*>(g_h0)[w * 32 + lane] = pack_half4(v);
        const float* kr = ak;
        const float* kt = ak + 3 * DD;
        float4 a1 = reinterpret_cast<const float4*>(kr)[lane];
        float4 a2 = reinterpret_cast<const float4*>(kr + DD)[lane];
        float4 b1 = reinterpret_cast<const float4*>(kt)[lane];
        float4 b2 = reinterpret_cast<const float4*>(kt + DD)[lane];
        float s1 = wsum(dot4(v, a1));
        float s2 = wsum(dot4(v, a2));
        float s3 = wsum(dot4(v, b1));
        float s4 = wsum(dot4(v, b2));
        if (lane == 0) {
            g_p1r[w] = s1; g_p2r[w] = s2;
            g_p1t[w] = s3; g_p2t[w] = s4;
        }
    } else if (w < n + r + t) {
        int q = w - n;                      // [0, r+t): rel rows first, then time rows
        int isTim = (q >= r) ? 1 : 0;
        const float* src = isTim ? (tim + (size_t)(q - r) * DD)
                                 : (rel + (size_t)q * DD);
        float4 v = reinterpret_cast<const float4*>(src)[lane];
        reinterpret_cast<uint2*>(g_hemb)[q * 32 + lane] = pack_half4(v);
        float nn = wsum(dot4(v, v));
        if (lane == 0) g_nrm[q] = sqrtf(nn);
#pragma unroll
        for (int l = 0; l < 2; l++) {
            const float* kk = ak + (size_t)(l * 2 + isTim) * 3 * DD;
            float4 k2 = reinterpret_cast<const float4*>(kk + DD)[lane];
            float4 k3 = reinterpret_cast<const float4*>(kk + 2 * DD)[lane];
            float u2 = wsum(dot4(v, k2));
            float u3 = wsum(dot4(v, k3));
            if (lane == 0) { g_u2[l][q] = u2; g_u3[l][q] = u3; }
        }
    }
}

// single-launch scan with decoupled lookback (NPART=196 blocks co-resident)
__global__ void k_scan(int n, int e) {
    __shared__ int sh[SCAN_B / 32];
    __shared__ int shoff;
    int tid = threadIdx.x, lane = tid & 31, wid = tid >> 5;
    int bid = blockIdx.x;
    int i = bid * SCAN_B + tid;
    int v = (i < n) ? g_cnt[i] : 0;

    int bs = v;
#pragma unroll
    for (int o = 16; o > 0; o >>= 1) bs += __shfl_down_sync(0xffffffffu, bs, o);
    if (lane == 0) sh[wid] = bs;
    __syncthreads();
    if (tid == 0) {
        int s = 0;
#pragma unroll
        for (int k = 0; k < SCAN_B / 32; k++) s += sh[k];
        atomicExch(&g_part[bid], s + 1);
    }
    __syncthreads();

    int pv = 0;
    if (tid < bid) {
        int x;
        do { x = atomicAdd(&g_part[tid], 0); } while (x == 0);
        pv = x - 1;
    }
    int ps = pv;
#pragma unroll
    for (int o = 16; o > 0; o >>= 1) ps += __shfl_down_sync(0xffffffffu, ps, o);
    if (lane == 0) sh[wid] = ps;
    __syncthreads();
    if (tid == 0) {
        int s = 0;
#pragma unroll
        for (int k = 0; k < SCAN_B / 32; k++) s += sh[k];
        shoff = s;
    }
    __syncthreads();

    int x = v;
#pragma unroll
    for (int o = 1; o < 32; o <<= 1) {
        int y = __shfl_up_sync(0xffffffffu, x, o);
        if (lane >= o) x += y;
    }
    if (lane == 31) sh[wid] = x;
    __syncthreads();
    if (wid == 0) {
        int s = (lane < SCAN_B / 32) ? sh[lane] : 0;
#pragma unroll
        for (int o = 1; o < 32; o <<= 1) {
            int y = __shfl_up_sync(0xffffffffu, s, o);
            if (lane >= o) s += y;
        }
        if (lane < SCAN_B / 32) sh[lane] = s;
    }
    __syncthreads();
    int woff = (wid > 0) ? sh[wid - 1] : 0;
    int excl = x + woff - v + shoff;
    if (i < n) g_rowptr[i] = excl;
    if (i == n - 1) g_rowptr[n] = e;
}

// fused: 16-lane edge scores + atomic-free CSR scatter; restores g_cnt/g_part
__global__ void k_score_scatter(const __half* __restrict__ fh,
                                const int* __restrict__ arow,
                                const int* __restrict__ acol,
                                const int* __restrict__ rcol,
                                const int* __restrict__ tcol,
                                const float* __restrict__ val,
                                int n, int r, int layer, int e) {
    int tid = blockIdx.x * blockDim.x + threadIdx.x;
    if (e > 0) {
        if (tid < n) g_cnt[tid] = 0;
        if (tid < NPART) g_part[tid] = 0;
        if (tid < e) {
            int p = g_rowptr[arow[tid]] + g_rank[tid];
            g_ecol[p] = acol[tid];
        }
    }
    int g = tid >> 4;
    int sl = tid & 15;
    if (g >= n) return;
    int row = arow[g];
    int col = acol[g];
    int rc  = rcol[g];
    int tc  = tcol[g] + r;
    float v = val[g];
    const uint4* fh4 = reinterpret_cast<const uint4*>(fh);
    const uint4* eh4 = reinterpret_cast<const uint4*>(g_hemb);
    uint4 uf = fh4[col * 16 + sl];
    uint4 ur = eh4[rc * 16 + sl];
    uint4 ut = eh4[tc * 16 + sl];
    float dr = dot8h(uf, ur);
    float dt = dot8h(uf, ut);
#pragma unroll
    for (int o = 8; o > 0; o >>= 1) {
        dr += __shfl_down_sync(0xffffffffu, dr, o, 16);
        dt += __shfl_down_sync(0xffffffffu, dt, o, 16);
    }
    if (sl == 0) {
        float cr = v / fmaxf(v * g_nrm[rc], 1e-12f);
        float ct = v / fmaxf(v * g_nrm[tc], 1e-12f);
        float s = g_p1r[row] + g_p2r[col]
                - 2.f * cr * cr * dr * g_u2[layer][rc] + cr * g_u3[layer][rc]
                + g_p1t[row] + g_p2t[col]
                - 2.f * ct * ct * dt * g_u2[layer][tc] + ct * g_u3[layer][tc];
        g_score[g] = s;
    }
}

// one warp per row. Specialized deg<=32 path:
//  max-butterfly (no exp) -> one exp per lane -> stage (ex, col) float2 in smem
//  -> sum-butterfly -> consume with packed f32x2 FMA.
__global__ void k_agg(const __half* __restrict__ fh,
                      float* __restrict__ out, int n,
                      __half* __restrict__ outh,
                      const float* __restrict__ nkr,
                      const float* __restrict__ nkt) {
    __shared__ float2 stg[8][32];    // (ex, col-as-int-bits)
    int w = (blockIdx.x * blockDim.x + threadIdx.x) >> 5;
    int lane = threadIdx.x & 31;
    int wid = threadIdx.x >> 5;
    if (w >= n) return;
    int beg = g_rowptr[w], end = g_rowptr[w + 1];
    int deg = end - beg;

    unsigned long long acc1 = pack_f32x2(0.f, 0.f);
    unsigned long long acc2 = acc1;
    float s;

    if (deg <= 32) {
        int c = -1;
        float a = -INFINITY;
        if (lane < deg) {
            c = g_ecol[beg + lane];
            a = g_score[c];
        }
        // warp max (butterfly)
        float mm = a;
#pragma unroll
        for (int o = 16; o > 0; o >>= 1)
            mm = fmaxf(mm, __shfl_xor_sync(0xffffffffu, mm, o));
        float ex = (lane < deg) ? __expf(a - mm) : 0.f;
        stg[wid][lane] = make_float2(ex, __int_as_float(c));
        __syncwarp();
        // warp sum (butterfly)
        float ss = ex;
#pragma unroll
        for (int o = 16; o > 0; o >>= 1)
            ss += __shfl_xor_sync(0xffffffffu, ss, o);
        s = ss;
#pragma unroll 4
        for (int k = 0; k < deg; k++) {
            float2 p = stg[wid][k];
            int ck = __float_as_int(p.y);
            unsigned long long wk2 = pack_f32x2(p.x, p.x);
            uint2 u = reinterpret_cast<const uint2*>(fh)[ck * 32 + lane];
            unsigned long long f1, f2;
            h4_to_f32x2(u, f1, f2);
            FMA_F32X2(acc1, wk2, f1);
            FMA_F32X2(acc2, wk2, f2);
        }
    } else {
        // generic path: global max first, then chunked stage/consume
        float mm = -INFINITY;
        for (int j = beg + lane; j < end; j += 32)
            mm = fmaxf(mm, g_score[g_ecol[j]]);
#pragma unroll
        for (int o = 16; o > 0; o >>= 1)
            mm = fmaxf(mm, __shfl_xor_sync(0xffffffffu, mm, o));
        s = 0.f;
        for (int base = 0; base < deg; base += 32) {
            int j = beg + base + lane;
            float ex = 0.f;
            int c = -1;
            if (j < end) {
                c = g_ecol[j];
                ex = __expf(g_score[c] - mm);
            }
            stg[wid][lane] = make_float2(ex, __int_as_float(c));
            __syncwarp();
            float ss = ex;
#pragma unroll
            for (int o = 16; o > 0; o >>= 1)
                ss += __shfl_xor_sync(0xffffffffu, ss, o);
            s += ss;
            int lim = min(32, deg - base);
#pragma unroll 4
            for (int k = 0; k < lim; k++) {
                float2 p = stg[wid][k];
                int ck = __float_as_int(p.y);
                unsigned long long wk2 = pack_f32x2(p.x, p.x);
                uint2 u = reinterpret_cast<const uint2*>(fh)[ck * 32 + lane];
                unsigned long long f1, f2;
                h4_to_f32x2(u, f1, f2);
                FMA_F32X2(acc1, wk2, f1);
                FMA_F32X2(acc2, wk2, f2);
            }
            __syncwarp();
        }
    }

    float inv = (s > 0.f) ? (1.f / s) : 0.f;
    float2 a1 = unpack_f32x2(acc1);
    float2 a2 = unpack_f32x2(acc2);
    float4 o;
    o.x = fmaxf(a1.x * inv, 0.f);
    o.y = fmaxf(a1.y * inv, 0.f);
    o.z = fmaxf(a2.x * inv, 0.f);
    o.w = fmaxf(a2.y * inv, 0.f);
    reinterpret_cast<float4*>(out)[w * 32 + lane] = o;

    if (outh) {   // fp16 mirror for next layer's gathers + fused next-layer node dots
        reinterpret_cast<uint2*>(outh)[w * 32 + lane] = pack_half4(o);
        float4 k1 = reinterpret_cast<const float4*>(nkr)[lane];
        float4 k2 = reinterpret_cast<const float4*>(nkr + DD)[lane];
        float4 k3 = reinterpret_cast<const float4*>(nkt)[lane];
        float4 k4 = reinterpret_cast<const float4*>(nkt + DD)[lane];
        float s1 = wsum(dot4(o, k1));
        float s2 = wsum(dot4(o, k2));
        float s3 = wsum(dot4(o, k3));
        float s4 = wsum(dot4(o, k4));
        if (lane == 0) {
            g_p1r[w] = s1; g_p2r[w] = s2;
            g_p1t[w] = s3; g_p2t[w] = s4;
        }
    }
}

extern "C" void kernel_launch(void* const* d_in, const int* in_sizes, int n_in,
                              void* d_out, int out_size) {
    const float* features = (const float*)d_in[0];
    const float* rel      = (const float*)d_in[1];
    const float* tim      = (const float*)d_in[2];
    const float* val      = (const float*)d_in[3];
    const float* ak       = (const float*)d_in[4];
    const int*   arow     = (const int*)d_in[5];
    const int*   acol     = (const int*)d_in[6];
    const int*   rcol     = (const int*)d_in[7];
    const int*   tcol     = (const int*)d_in[8];
    float* out = (float*)d_out;

    int n = in_sizes[0] / DD;   // 50000
    int e = in_sizes[5];        // 600000
    int r = in_sizes[1] / DD;   // 1000
    int t = in_sizes[2] / DD;   // 500

    void* h0p = nullptr; cudaGetSymbolAddress(&h0p, g_h0);
    void* h1p = nullptr; cudaGetSymbolAddress(&h1p, g_h1);
    const __half* h0 = (const __half*)h0p;
    __half* h1 = (__half*)h1p;

    int gridN  = (n * 32 + 255) / 256;
    int fusedThreads = max(n * 16, e);
    int gridF = (fusedThreads + 255) / 256;
    int gridN16 = (n * 16 + 255) / 256;

    // 1: fused copy + relu + node dots + emb mirrors/dots + edge counting/ranks
    int prepWarps = n + r + t;
    k_prep<<<(prepWarps * 32 + 255) / 256, 256>>>(features, out, rel, tim, ak,
                                                  arow, n, r, t, e);
    // 2: single-launch lookback scan
    k_scan<<<NPART, SCAN_B>>>(n, e);
    // 3: fused layer-0 scores + CSR scatter (+ state restore)
    k_score_scatter<<<gridF, 256>>>(h0, arow, acol, rcol, tcol, val, n, r, 0, e);
    // 4: layer-0 aggregate (PROFILED SLOT; fuses fp16 mirror + layer-1 node dots)
    k_agg<<<gridN, 256>>>(h0, out + (size_t)n * DD, n, h1,
                          ak + (size_t)2 * 3 * DD, ak + (size_t)3 * 3 * DD);
    // 5-6: layer 1
    k_score_scatter<<<gridN16, 256>>>(h1, arow, acol, rcol, tcol, val, n, r, 1, 0);
    k_agg<<<gridN, 256>>>(h1, out + (size_t)2 * n * DD, n, nullptr, nullptr, nullptr);
}

// round 15
// speedup vs baseline: 1.2176x; 1.0658x over previous
#include <cuda_runtime.h>
#include <cuda_fp16.h>
#include <math.h>

#define NN 50000
#define EE 600000
#define DD 128
#define RR 1000
#define TT 500
#define SCAN_B 256
#define NPART  ((NN + SCAN_B - 1) / SCAN_B)   // 196

// scratch (static device globals — no allocation; zero-initialized at load)
__device__ __half g_h0[NN * DD];                // relu(features), fp16 mirror
__device__ __half g_h1[NN * DD];                // layer-1 features, fp16 mirror
__device__ __half g_hemb[(RR + TT) * DD];       // fp16 mirror of rel|time embeddings
__device__ float g_score[NN];                   // combined edge scores (only first N used)
__device__ float g_p1r[NN], g_p2r[NN], g_p1t[NN], g_p2t[NN];
__device__ float g_nrm[RR + TT];
__device__ float g_u2[2][RR + TT], g_u3[2][RR + TT];
__device__ int   g_cnt[NN];                     // re-zeroed by score_scatter each call
__device__ int   g_rowptr[NN + 1];
__device__ int   g_rank[EE];                    // within-row rank of each edge
__device__ int   g_ecol[EE];                    // acol values in CSR order
__device__ int   g_part[NPART];                 // lookback flags: 0=pending, sum+1=ready

__device__ __forceinline__ float wsum(float v) {
#pragma unroll
    for (int o = 16; o > 0; o >>= 1) v += __shfl_down_sync(0xffffffffu, v, o);
    return v;
}

__device__ __forceinline__ float dot4(float4 a, float4 b) {
    return a.x * b.x + a.y * b.y + a.z * b.z + a.w * b.w;
}

__device__ __forceinline__ uint2 pack_half4(float4 v) {
    __half2 a = __floats2half2_rn(v.x, v.y);
    __half2 b = __floats2half2_rn(v.z, v.w);
    uint2 u;
    u.x = *reinterpret_cast<unsigned*>(&a);
    u.y = *reinterpret_cast<unsigned*>(&b);
    return u;
}

__device__ __forceinline__ float4 unpack_half4(uint2 u) {
    __half2 a = *reinterpret_cast<__half2*>(&u.x);
    __half2 b = *reinterpret_cast<__half2*>(&u.y);
    float2 f1 = __half22float2(a);
    float2 f2 = __half22float2(b);
    return make_float4(f1.x, f1.y, f2.x, f2.y);
}

__device__ __forceinline__ float dot8h(uint4 a, uint4 b) {
    float4 a1 = unpack_half4(make_uint2(a.x, a.y));
    float4 a2 = unpack_half4(make_uint2(a.z, a.w));
    float4 b1 = unpack_half4(make_uint2(b.x, b.y));
    float4 b2 = unpack_half4(make_uint2(b.z, b.w));
    return dot4(a1, b1) + dot4(a2, b2);
}

// packed f32x2 FMA: acc = a * b + acc   (2 fp32 lanes in one instruction)
#define FMA_F32X2(acc, a, b) \
    asm("fma.rn.f32x2 %0, %1, %2, %0;" : "+l"(acc) : "l"(a), "l"(b))

__device__ __forceinline__ unsigned long long pack_f32x2(float lo, float hi) {
    unsigned long long u;
    asm("mov.b64 %0, {%1, %2};" : "=l"(u) : "f"(lo), "f"(hi));
    return u;
}

__device__ __forceinline__ float2 unpack_f32x2(unsigned long long u) {
    float lo, hi;
    asm("mov.b64 {%0, %1}, %2;" : "=f"(lo), "=f"(hi) : "l"(u));
    return make_float2(lo, hi);
}

// half2 pair -> packed f32x2 pair
__device__ __forceinline__ void h4_to_f32x2(uint2 u, unsigned long long& p1,
                                            unsigned long long& p2) {
    float2 f1 = __half22float2(*reinterpret_cast<__half2*>(&u.x));
    float2 f2 = __half22float2(*reinterpret_cast<__half2*>(&u.y));
    p1 = pack_f32x2(f1.x, f1.y);
    p2 = pack_f32x2(f2.x, f2.y);
}

// fused mega-prep:
//  warps [0, n):        out[0]=features copy, relu->g_h0 (fp16), layer-0 node dots
//  warps [n, n+r+t):    emb fp16 mirror, norm, u2/u3 for both layers
//  threads [0, e):      edge row counting; rank = atomic return value
__global__ void k_prep(const float* __restrict__ features,
                       float* __restrict__ out,
                       const float* __restrict__ rel,
                       const float* __restrict__ tim,
                       const float* __restrict__ ak,
                       const int* __restrict__ arow,
                       int n, int r, int t, int e) {
    int tid = blockIdx.x * blockDim.x + threadIdx.x;
    if (tid < e) g_rank[tid] = atomicAdd(&g_cnt[arow[tid]], 1);
    int w = tid >> 5, lane = tid & 31;
    if (w < n) {
        float4 v = reinterpret_cast<const float4*>(features)[w * 32 + lane];
        reinterpret_cast<float4*>(out)[w * 32 + lane] = v;   // output[0] = raw features
        v.x = fmaxf(v.x, 0.f); v.y = fmaxf(v.y, 0.f);
        v.z = fmaxf(v.z, 0.f); v.w = fmaxf(v.w, 0.f);
        reinterpret_cast<uint2*>(g_h0)[w * 32 + lane] = pack_half4(v);
        const float* kr = ak;
        const float* kt = ak + 3 * DD;
        float4 a1 = reinterpret_cast<const float4*>(kr)[lane];
        float4 a2 = reinterpret_cast<const float4*>(kr + DD)[lane];
        float4 b1 = reinterpret_cast<const float4*>(kt)[lane];
        float4 b2 = reinterpret_cast<const float4*>(kt + DD)[lane];
        float s1 = wsum(dot4(v, a1));
        float s2 = wsum(dot4(v, a2));
        float s3 = wsum(dot4(v, b1));
        float s4 = wsum(dot4(v, b2));
        if (lane == 0) {
            g_p1r[w] = s1; g_p2r[w] = s2;
            g_p1t[w] = s3; g_p2t[w] = s4;
        }
    } else if (w < n + r + t) {
        int q = w - n;                      // [0, r+t): rel rows first, then time rows
        int isTim = (q >= r) ? 1 : 0;
        const float* src = isTim ? (tim + (size_t)(q - r) * DD)
                                 : (rel + (size_t)q * DD);
        float4 v = reinterpret_cast<const float4*>(src)[lane];
        reinterpret_cast<uint2*>(g_hemb)[q * 32 + lane] = pack_half4(v);
        float nn = wsum(dot4(v, v));
        if (lane == 0) g_nrm[q] = sqrtf(nn);
#pragma unroll
        for (int l = 0; l < 2; l++) {
            const float* kk = ak + (size_t)(l * 2 + isTim) * 3 * DD;
            float4 k2 = reinterpret_cast<const float4*>(kk + DD)[lane];
            float4 k3 = reinterpret_cast<const float4*>(kk + 2 * DD)[lane];
            float u2 = wsum(dot4(v, k2));
            float u3 = wsum(dot4(v, k3));
            if (lane == 0) { g_u2[l][q] = u2; g_u3[l][q] = u3; }
        }
    }
}

// single-launch scan with decoupled lookback (NPART=196 blocks co-resident)
__global__ void k_scan(int n, int e) {
    __shared__ int sh[SCAN_B / 32];
    __shared__ int shoff;
    int tid = threadIdx.x, lane = tid & 31, wid = tid >> 5;
    int bid = blockIdx.x;
    int i = bid * SCAN_B + tid;
    int v = (i < n) ? g_cnt[i] : 0;

    int bs = v;
#pragma unroll
    for (int o = 16; o > 0; o >>= 1) bs += __shfl_down_sync(0xffffffffu, bs, o);
    if (lane == 0) sh[wid] = bs;
    __syncthreads();
    if (tid == 0) {
        int s = 0;
#pragma unroll
        for (int k = 0; k < SCAN_B / 32; k++) s += sh[k];
        atomicExch(&g_part[bid], s + 1);
    }
    __syncthreads();

    int pv = 0;
    if (tid < bid) {
        int x;
        do { x = atomicAdd(&g_part[tid], 0); } while (x == 0);
        pv = x - 1;
    }
    int ps = pv;
#pragma unroll
    for (int o = 16; o > 0; o >>= 1) ps += __shfl_down_sync(0xffffffffu, ps, o);
    if (lane == 0) sh[wid] = ps;
    __syncthreads();
    if (tid == 0) {
        int s = 0;
#pragma unroll
        for (int k = 0; k < SCAN_B / 32; k++) s += sh[k];
        shoff = s;
    }
    __syncthreads();

    int x = v;
#pragma unroll
    for (int o = 1; o < 32; o <<= 1) {
        int y = __shfl_up_sync(0xffffffffu, x, o);
        if (lane >= o) x += y;
    }
    if (lane == 31) sh[wid] = x;
    __syncthreads();
    if (wid == 0) {
        int s = (lane < SCAN_B / 32) ? sh[lane] : 0;
#pragma unroll
        for (int o = 1; o < 32; o <<= 1) {
            int y = __shfl_up_sync(0xffffffffu, s, o);
            if (lane >= o) s += y;
        }
        if (lane < SCAN_B / 32) sh[lane] = s;
    }
    __syncthreads();
    int woff = (wid > 0) ? sh[wid - 1] : 0;
    int excl = x + woff - v + shoff;
    if (i < n) g_rowptr[i] = excl;
    if (i == n - 1) g_rowptr[n] = e;
}

// fused: 16-lane edge scores + atomic-free CSR scatter; restores g_cnt/g_part
__global__ void k_score_scatter(const __half* __restrict__ fh,
                                const int* __restrict__ arow,
                                const int* __restrict__ acol,
                                const int* __restrict__ rcol,
                                const int* __restrict__ tcol,
                                const float* __restrict__ val,
                                int n, int r, int layer, int e) {
    int tid = blockIdx.x * blockDim.x + threadIdx.x;
    if (e > 0) {
        if (tid < n) g_cnt[tid] = 0;
        if (tid < NPART) g_part[tid] = 0;
        if (tid < e) {
            int p = g_rowptr[arow[tid]] + g_rank[tid];
            g_ecol[p] = acol[tid];
        }
    }
    int g = tid >> 4;
    int sl = tid & 15;
    if (g >= n) return;
    int row = arow[g];
    int col = acol[g];
    int rc  = rcol[g];
    int tc  = tcol[g] + r;
    float v = val[g];
    const uint4* fh4 = reinterpret_cast<const uint4*>(fh);
    const uint4* eh4 = reinterpret_cast<const uint4*>(g_hemb);
    uint4 uf = fh4[col * 16 + sl];
    uint4 ur = eh4[rc * 16 + sl];
    uint4 ut = eh4[tc * 16 + sl];
    float dr = dot8h(uf, ur);
    float dt = dot8h(uf, ut);
#pragma unroll
    for (int o = 8; o > 0; o >>= 1) {
        dr += __shfl_down_sync(0xffffffffu, dr, o, 16);
        dt += __shfl_down_sync(0xffffffffu, dt, o, 16);
    }
    if (sl == 0) {
        float cr = v / fmaxf(v * g_nrm[rc], 1e-12f);
        float ct = v / fmaxf(v * g_nrm[tc], 1e-12f);
        float s = g_p1r[row] + g_p2r[col]
                - 2.f * cr * cr * dr * g_u2[layer][rc] + cr * g_u3[layer][rc]
                + g_p1t[row] + g_p2t[col]
                - 2.f * ct * ct * dt * g_u2[layer][tc] + ct * g_u3[layer][tc];
        g_score[g] = s;
    }
}

// one warp per row; (ex, col) broadcast via register shuffles (no smem staging).
// __launch_bounds__(256, 8) forces <=32 regs -> 64 resident warps/SM.
__global__ void __launch_bounds__(256, 8)
k_agg(const __half* __restrict__ fh,
      float* __restrict__ out, int n,
      __half* __restrict__ outh,
      const float* __restrict__ nkr,
      const float* __restrict__ nkt) {
    const unsigned FULL = 0xffffffffu;
    int w = (blockIdx.x * blockDim.x + threadIdx.x) >> 5;
    int lane = threadIdx.x & 31;
    if (w >= n) return;
    int beg = g_rowptr[w], end = g_rowptr[w + 1];
    int deg = end - beg;

    unsigned long long acc1 = pack_f32x2(0.f, 0.f);
    unsigned long long acc2 = acc1;
    float s;

    if (deg <= 32) {
        int c = 0;
        float a = -INFINITY;
        if (lane < deg) {
            c = g_ecol[beg + lane];
            a = g_score[c];
        }
        float mm = a;
#pragma unroll
        for (int o = 16; o > 0; o >>= 1)
            mm = fmaxf(mm, __shfl_xor_sync(FULL, mm, o));
        float ex = (lane < deg) ? __expf(a - mm) : 0.f;
        float ss = ex;
#pragma unroll
        for (int o = 16; o > 0; o >>= 1)
            ss += __shfl_xor_sync(FULL, ss, o);
        s = ss;
#pragma unroll 4
        for (int k = 0; k < deg; k++) {
            float exk = __shfl_sync(FULL, ex, k);
            int   ck  = __shfl_sync(FULL, c, k);
            unsigned long long wk2 = pack_f32x2(exk, exk);
            uint2 u = reinterpret_cast<const uint2*>(fh)[ck * 32 + lane];
            unsigned long long f1, f2;
            h4_to_f32x2(u, f1, f2);
            FMA_F32X2(acc1, wk2, f1);
            FMA_F32X2(acc2, wk2, f2);
        }
    } else {
        // generic path: global max first, then chunked shuffle-broadcast consume
        float mm = -INFINITY;
        for (int j = beg + lane; j < end; j += 32)
            mm = fmaxf(mm, g_score[g_ecol[j]]);
#pragma unroll
        for (int o = 16; o > 0; o >>= 1)
            mm = fmaxf(mm, __shfl_xor_sync(FULL, mm, o));
        s = 0.f;
        for (int base = 0; base < deg; base += 32) {
            int j = beg + base + lane;
            float ex = 0.f;
            int c = 0;
            if (j < end) {
                c = g_ecol[j];
                ex = __expf(g_score[c] - mm);
            }
            float ss = ex;
#pragma unroll
            for (int o = 16; o > 0; o >>= 1)
                ss += __shfl_xor_sync(FULL, ss, o);
            s += ss;
            int lim = min(32, deg - base);
#pragma unroll 4
            for (int k = 0; k < lim; k++) {
                float exk = __shfl_sync(FULL, ex, k);
                int   ck  = __shfl_sync(FULL, c, k);
                unsigned long long wk2 = pack_f32x2(exk, exk);
                uint2 u = reinterpret_cast<const uint2*>(fh)[ck * 32 + lane];
                unsigned long long f1, f2;
                h4_to_f32x2(u, f1, f2);
                FMA_F32X2(acc1, wk2, f1);
                FMA_F32X2(acc2, wk2, f2);
            }
        }
    }

    float inv = (s > 0.f) ? (1.f / s) : 0.f;
    float2 a1 = unpack_f32x2(acc1);
    float2 a2 = unpack_f32x2(acc2);
    float4 o;
    o.x = fmaxf(a1.x * inv, 0.f);
    o.y = fmaxf(a1.y * inv, 0.f);
    o.z = fmaxf(a2.x * inv, 0.f);
    o.w = fmaxf(a2.y * inv, 0.f);
    reinterpret_cast<float4*>(out)[w * 32 + lane] = o;

    if (outh) {   // fp16 mirror for next layer's gathers + fused next-layer node dots
        reinterpret_cast<uint2*>(outh)[w * 32 + lane] = pack_half4(o);
        float4 k1 = reinterpret_cast<const float4*>(nkr)[lane];
        float4 k2 = reinterpret_cast<const float4*>(nkr + DD)[lane];
        float4 k3 = reinterpret_cast<const float4*>(nkt)[lane];
        float4 k4 = reinterpret_cast<const float4*>(nkt + DD)[lane];
        float s1 = wsum(dot4(o, k1));
        float s2 = wsum(dot4(o, k2));
        float s3 = wsum(dot4(o, k3));
        float s4 = wsum(dot4(o, k4));
        if (lane == 0) {
            g_p1r[w] = s1; g_p2r[w] = s2;
            g_p1t[w] = s3; g_p2t[w] = s4;
        }
    }
}

extern "C" void kernel_launch(void* const* d_in, const int* in_sizes, int n_in,
                              void* d_out, int out_size) {
    const float* features = (const float*)d_in[0];
    const float* rel      = (const float*)d_in[1];
    const float* tim      = (const float*)d_in[2];
    const float* val      = (const float*)d_in[3];
    const float* ak       = (const float*)d_in[4];
    const int*   arow     = (const int*)d_in[5];
    const int*   acol     = (const int*)d_in[6];
    const int*   rcol     = (const int*)d_in[7];
    const int*   tcol     = (const int*)d_in[8];
    float* out = (float*)d_out;

    int n = in_sizes[0] / DD;   // 50000
    int e = in_sizes[5];        // 600000
    int r = in_sizes[1] / DD;   // 1000
    int t = in_sizes[2] / DD;   // 500

    void* h0p = nullptr; cudaGetSymbolAddress(&h0p, g_h0);
    void* h1p = nullptr; cudaGetSymbolAddress(&h1p, g_h1);
    const __half* h0 = (const __half*)h0p;
    __half* h1 = (__half*)h1p;

    int gridN  = (n * 32 + 255) / 256;
    int fusedThreads = max(n * 16, e);
    int gridF = (fusedThreads + 255) / 256;
    int gridN16 = (n * 16 + 255) / 256;

    // 1: fused copy + relu + node dots + emb mirrors/dots + edge counting/ranks
    int prepWarps = n + r + t;
    k_prep<<<(prepWarps * 32 + 255) / 256, 256>>>(features, out, rel, tim, ak,
                                                  arow, n, r, t, e);
    // 2: single-launch lookback scan
    k_scan<<<NPART, SCAN_B>>>(n, e);
    // 3: fused layer-0 scores + CSR scatter (+ state restore)
    k_score_scatter<<<gridF, 256>>>(h0, arow, acol, rcol, tcol, val, n, r, 0, e);
    // 4: layer-0 aggregate (PROFILED SLOT; fuses fp16 mirror + layer-1 node dots)
    k_agg<<<gridN, 256>>>(h0, out + (size_t)n * DD, n, h1,
                          ak + (size_t)2 * 3 * DD, ak + (size_t)3 * 3 * DD);
    // 5-6: layer 1
    k_score_scatter<<<gridN16, 256>>>(h1, arow, acol, rcol, tcol, val, n, r, 1, 0);
    k_agg<<<gridN, 256>>>(h1, out + (size_t)2 * n * DD, n, nullptr, nullptr, nullptr);
}